// round 2
// baseline (speedup 1.0000x reference)
#include <cuda_runtime.h>
#include <math.h>

#define NN 50000
#define EE 800000
#define DD 128
#define NB 5
#define GG 512
#define NC 10
#define FD (NB*DD)            // 640
#define ONE_PLUS_EPS 129.0f   // (1 + eps), eps = 128
#define BN_EPS 1e-5f

// ---------------- scratch (static device globals; no allocation) ----------------
__device__ __align__(16) float g_xcur[NN*DD];
__device__ __align__(16) float g_h0[NN*DD];
__device__ __align__(16) float g_hp1[NN*DD];
__device__ __align__(16) float g_hp2[NN*DD];
__device__ __align__(16) float g_feats[GG*FD];
__device__ float g_stats[2*DD];
__device__ float g_scale[DD];
__device__ float g_shift[DD];
__device__ float g_cscale[FD];
__device__ float g_cshift[FD];
__device__ __align__(16) float g_fmlp[GG*DD];
__device__ int g_src[EE];
__device__ int g_dst[EE];
__device__ int g_batch[NN];
__device__ int g_rowptr[NN+1];
__device__ int g_cnt[NN];
__device__ int g_esrc[EE];
__device__ int g_is64;

// ---------------- dtype probe: int32 vs int64 edge_index ----------------
__global__ void detect_kernel(const void* ei) {
    const int* p = (const int*)ei;
    int t = threadIdx.x;                 // 128 threads
    __shared__ int nz;
    if (t == 0) nz = 0;
    __syncthreads();
    // If int64 (values < 2^31), every high word is 0. If int32, p[2t+1] are
    // random src indices in [0,50000) — all-zero has probability ~0.
    if (p[2*t + 1] != 0) atomicOr(&nz, 1);
    __syncthreads();
    if (t == 0) g_is64 = nz ? 0 : 1;
}

__global__ void convert_kernel(const void* ei, const void* bt) {
    int idx = blockIdx.x * blockDim.x + threadIdx.x;
    int is64 = g_is64;
    const int* p = (const int*)ei;
    const int* b = (const int*)bt;
    if (idx < EE) {
        if (is64) { g_src[idx] = p[2*idx]; g_dst[idx] = p[2*(EE+idx)]; }
        else      { g_src[idx] = p[idx];   g_dst[idx] = p[EE+idx]; }
    }
    if (idx < NN) {
        g_batch[idx] = is64 ? b[2*idx] : b[idx];
    }
}

// ---------------- init: copy x, zero accumulators ----------------
__global__ void init_kernel(const float* __restrict__ x) {
    int idx = blockIdx.x * blockDim.x + threadIdx.x;  // exactly NN*DD threads
    if (idx < NN*DD) g_xcur[idx] = x[idx];
    if (idx < GG*FD) g_feats[idx] = 0.f;
    if (idx < NN)    g_cnt[idx] = 0;
    if (idx < 2*DD)  g_stats[idx] = 0.f;
}

// ---------------- CSR build ----------------
__global__ void hist_kernel() {
    int e = blockIdx.x * blockDim.x + threadIdx.x;
    if (e < EE) atomicAdd(&g_cnt[g_dst[e]], 1);
}

__global__ void scan_kernel() {
    __shared__ int s[1024];
    __shared__ int carry;
    int t = threadIdx.x;
    if (t == 0) carry = 0;
    __syncthreads();
    for (int base = 0; base <= NN; base += 1024) {
        int i = base + t;
        int v = (i < NN) ? g_cnt[i] : 0;
        s[t] = v;
        __syncthreads();
        for (int off = 1; off < 1024; off <<= 1) {
            int tmp = (t >= off) ? s[t - off] : 0;
            __syncthreads();
            s[t] += tmp;
            __syncthreads();
        }
        if (i <= NN) g_rowptr[i] = carry + s[t] - v;  // exclusive prefix
        if (i < NN)  g_cnt[i] = 0;                    // reuse as scatter cursor
        __syncthreads();
        if (t == 0) carry += s[1023];
        __syncthreads();
    }
}

__global__ void scatter_kernel() {
    int e = blockIdx.x * blockDim.x + threadIdx.x;
    if (e < EE) {
        int d = g_dst[e];
        int pos = g_rowptr[d] + atomicAdd(&g_cnt[d], 1);
        g_esrc[pos] = g_src[e];
    }
}

// ---------------- GIN aggregation: h0 = (1+eps)*x + sum_{src->n} x[src] ----------------
__global__ void agg_kernel() {
    int n = blockIdx.x;          // one CTA per node
    int d = threadIdx.x;         // 128 threads = feature dim
    __shared__ int se[DD];
    int beg = g_rowptr[n], end = g_rowptr[n+1];
    float acc = ONE_PLUS_EPS * g_xcur[n*DD + d];
    for (int base = beg; base < end; base += DD) {
        int cnt = min(DD, end - base);
        if (d < cnt) se[d] = g_esrc[base + d];
        __syncthreads();
        for (int j = 0; j < cnt; j++)
            acc += g_xcur[se[j]*DD + d];
        __syncthreads();
    }
    g_h0[n*DD + d] = acc;
}

// ---------------- GEMM + bias + relu + per-column stat accumulation ----------------
// PHASE 0: out = relu(g_h0 @ W + b)                  -> g_hp1
// PHASE 1: out = relu(bn(g_hp1) @ W + b)             -> g_hp2   (bn via g_scale/g_shift)
template<int PHASE>
__global__ void __launch_bounds__(256) gemm_kernel(const float* __restrict__ W,
                                                   const float* __restrict__ bias)
{
    const float* A = (PHASE == 0) ? g_h0 : g_hp1;
    float* out     = (PHASE == 0) ? g_hp1 : g_hp2;
    __shared__ float sA[64][36];     // 64 rows x 32 k (padded)
    __shared__ float sW[32][132];    // 32 k x 128 n (padded)
    __shared__ float ssum[DD], ssq[DD];

    int t = threadIdx.x;
    int row0 = blockIdx.x * 64;
    int tx = t & 31, ty = t >> 5;

    float acc[8][4];
    #pragma unroll
    for (int i = 0; i < 8; i++)
        #pragma unroll
        for (int j = 0; j < 4; j++) acc[i][j] = 0.f;

    for (int k0 = 0; k0 < DD; k0 += 32) {
        __syncthreads();
        // W tile: 32x128 = 1024 float4 / 256 threads = 4 each
        #pragma unroll
        for (int l = 0; l < 4; l++) {
            int idx = t + l*256;
            int kk = idx >> 5, c4 = idx & 31;
            float4 w = reinterpret_cast<const float4*>(W)[(k0+kk)*32 + c4];
            sW[kk][c4*4+0] = w.x; sW[kk][c4*4+1] = w.y;
            sW[kk][c4*4+2] = w.z; sW[kk][c4*4+3] = w.w;
        }
        // A tile: 64x32 = 512 float4 / 256 threads = 2 each
        #pragma unroll
        for (int l = 0; l < 2; l++) {
            int idx = t + l*256;
            int r = idx >> 3, c4 = idx & 7;
            int gr = row0 + r;
            float4 a = make_float4(0.f, 0.f, 0.f, 0.f);
            if (gr < NN) a = reinterpret_cast<const float4*>(A)[gr*32 + (k0>>2) + c4];
            if (PHASE == 1) {
                int k = k0 + c4*4;
                a.x = a.x*g_scale[k+0] + g_shift[k+0];
                a.y = a.y*g_scale[k+1] + g_shift[k+1];
                a.z = a.z*g_scale[k+2] + g_shift[k+2];
                a.w = a.w*g_scale[k+3] + g_shift[k+3];
            }
            sA[r][c4*4+0] = a.x; sA[r][c4*4+1] = a.y;
            sA[r][c4*4+2] = a.z; sA[r][c4*4+3] = a.w;
        }
        __syncthreads();
        #pragma unroll
        for (int kk = 0; kk < 32; kk++) {
            float4 w = *reinterpret_cast<const float4*>(&sW[kk][tx*4]);
            #pragma unroll
            for (int rr = 0; rr < 8; rr++) {
                float a = sA[ty*8 + rr][kk];   // warp-broadcast
                acc[rr][0] += a * w.x;
                acc[rr][1] += a * w.y;
                acc[rr][2] += a * w.z;
                acc[rr][3] += a * w.w;
            }
        }
    }

    // epilogue: bias + relu + store + column stats
    if (t < DD) { ssum[t] = 0.f; ssq[t] = 0.f; }
    __syncthreads();
    float lsum[4] = {0,0,0,0}, lsq[4] = {0,0,0,0};
    #pragma unroll
    for (int rr = 0; rr < 8; rr++) {
        int gr = row0 + ty*8 + rr;
        if (gr < NN) {
            #pragma unroll
            for (int cc = 0; cc < 4; cc++) {
                int col = tx*4 + cc;
                float v = fmaxf(acc[rr][cc] + bias[col], 0.f);
                out[gr*DD + col] = v;
                lsum[cc] += v; lsq[cc] += v*v;
            }
        }
    }
    #pragma unroll
    for (int cc = 0; cc < 4; cc++) {
        atomicAdd(&ssum[tx*4 + cc], lsum[cc]);
        atomicAdd(&ssq[tx*4 + cc],  lsq[cc]);
    }
    __syncthreads();
    if (t < DD) {
        atomicAdd(&g_stats[t],      ssum[t]);
        atomicAdd(&g_stats[DD + t], ssq[t]);
    }
}

// stats -> per-column (scale, shift) for the following BN; re-zero stats
__global__ void finalize_kernel(const float* __restrict__ gamma,
                                const float* __restrict__ beta)
{
    int t = threadIdx.x;  // 128
    float s  = g_stats[t];
    float sq = g_stats[DD + t];
    float mu  = s / (float)NN;
    float var = sq / (float)NN - mu*mu;
    float r   = rsqrtf(var + BN_EPS);
    float sc  = gamma[t] * r;
    g_scale[t] = sc;
    g_shift[t] = beta[t] - mu*sc;
    g_stats[t] = 0.f;
    g_stats[DD + t] = 0.f;
}

// x_new = bn2(hp2); pooled feats[batch[n], blk*128 + d] += x_new
__global__ void bnpool_kernel(int blk) {
    int idx = blockIdx.x * blockDim.x + threadIdx.x;  // exactly NN*DD threads
    if (idx >= NN*DD) return;
    int n = idx >> 7, d = idx & 127;
    float v = g_hp2[idx] * g_scale[d] + g_shift[d];
    g_xcur[idx] = v;
    atomicAdd(&g_feats[g_batch[n]*FD + blk*DD + d], v);
}

// ---------------- classifier head ----------------
__global__ void cstats_kernel(const float* __restrict__ bn_g,
                              const float* __restrict__ bn_b)
{
    int c = blockIdx.x;   // 640 columns
    int t = threadIdx.x;  // 256
    float s = 0.f, sq = 0.f;
    for (int r = t; r < GG; r += 256) {
        float v = g_feats[r*FD + c];
        s += v; sq += v*v;
    }
    __shared__ float rs[256], rq[256];
    rs[t] = s; rq[t] = sq;
    __syncthreads();
    for (int off = 128; off > 0; off >>= 1) {
        if (t < off) { rs[t] += rs[t+off]; rq[t] += rq[t+off]; }
        __syncthreads();
    }
    if (t == 0) {
        float mu  = rs[0] / (float)GG;
        float var = rq[0] / (float)GG - mu*mu;
        float r   = rsqrtf(var + BN_EPS);
        float sc  = bn_g[c] * r;
        g_cscale[c] = sc;
        g_cshift[c] = bn_b[c] - mu*sc;
    }
}

__global__ void mlp1_kernel(const float* __restrict__ Wc1,
                            const float* __restrict__ bc1)
{
    int row = blockIdx.x;  // 512 graphs
    int t = threadIdx.x;   // 128 output cols
    __shared__ float sf[DD];
    float acc = 0.f;
    for (int kb = 0; kb < NB; kb++) {
        int k = kb*DD + t;
        sf[t] = g_feats[row*FD + k] * g_cscale[k] + g_cshift[k];
        __syncthreads();
        #pragma unroll 8
        for (int kk = 0; kk < DD; kk++)
            acc += sf[kk] * Wc1[(kb*DD + kk)*DD + t];
        __syncthreads();
    }
    g_fmlp[row*DD + t] = fmaxf(acc + bc1[t], 0.f);
}

__global__ void mlp2_kernel(const float* __restrict__ Wc2,
                            const float* __restrict__ bc2,
                            float* __restrict__ out)
{
    int warp = (blockIdx.x * blockDim.x + threadIdx.x) >> 5;
    int lane = threadIdx.x & 31;
    if (warp >= GG) return;
    float p[NC];
    #pragma unroll
    for (int c = 0; c < NC; c++) p[c] = 0.f;
    for (int k = lane; k < DD; k += 32) {
        float a = g_fmlp[warp*DD + k];
        #pragma unroll
        for (int c = 0; c < NC; c++) p[c] += a * Wc2[k*NC + c];
    }
    #pragma unroll
    for (int c = 0; c < NC; c++)
        #pragma unroll
        for (int off = 16; off > 0; off >>= 1)
            p[c] += __shfl_down_sync(0xffffffff, p[c], off);
    if (lane == 0) {
        float logits[NC];
        float mx = -1e30f;
        #pragma unroll
        for (int c = 0; c < NC; c++) { logits[c] = p[c] + bc2[c]; mx = fmaxf(mx, logits[c]); }
        float s = 0.f;
        #pragma unroll
        for (int c = 0; c < NC; c++) s += expf(logits[c] - mx);
        float lse = logf(s) + mx;
        #pragma unroll
        for (int c = 0; c < NC; c++) out[warp*NC + c] = logits[c] - lse;
    }
}

// ---------------- launch ----------------
extern "C" void kernel_launch(void* const* d_in, const int* in_sizes, int n_in,
                              void* d_out, int out_size)
{
    const float* x    = (const float*)d_in[0];
    const void*  ei   = d_in[1];
    const void*  bt   = d_in[2];
    const float* W1   = (const float*)d_in[3];
    const float* b1   = (const float*)d_in[4];
    const float* g1   = (const float*)d_in[5];
    const float* be1  = (const float*)d_in[6];
    const float* W2   = (const float*)d_in[7];
    const float* b2   = (const float*)d_in[8];
    const float* g2   = (const float*)d_in[9];
    const float* be2  = (const float*)d_in[10];
    const float* bng  = (const float*)d_in[11];
    const float* bnb  = (const float*)d_in[12];
    const float* Wc1  = (const float*)d_in[13];
    const float* bc1  = (const float*)d_in[14];
    const float* Wc2  = (const float*)d_in[15];
    const float* bc2  = (const float*)d_in[16];
    float* out = (float*)d_out;

    detect_kernel<<<1, 128>>>(ei);
    convert_kernel<<<(EE + 255)/256, 256>>>(ei, bt);
    init_kernel<<<(NN*DD + 255)/256, 256>>>(x);
    hist_kernel<<<(EE + 255)/256, 256>>>();
    scan_kernel<<<1, 1024>>>();
    scatter_kernel<<<(EE + 255)/256, 256>>>();

    const int gemm_grid = (NN + 63) / 64;  // 782
    for (int i = 0; i < NB; i++) {
        agg_kernel<<<NN, 128>>>();
        gemm_kernel<0><<<gemm_grid, 256>>>(W1 + i*DD*DD, b1 + i*DD);
        finalize_kernel<<<1, 128>>>(g1 + i*DD, be1 + i*DD);
        gemm_kernel<1><<<gemm_grid, 256>>>(W2 + i*DD*DD, b2 + i*DD);
        finalize_kernel<<<1, 128>>>(g2 + i*DD, be2 + i*DD);
        bnpool_kernel<<<(NN*DD + 255)/256, 256>>>(i);
    }

    cstats_kernel<<<FD, 256>>>(bng, bnb);
    mlp1_kernel<<<GG, 128>>>(Wc1, bc1);
    mlp2_kernel<<<(GG*32 + 255)/256, 256>>>(Wc2, bc2, out);
}

// round 4
// speedup vs baseline: 1.0744x; 1.0744x over previous
#include <cuda_runtime.h>
#include <cuda_bf16.h>
#include <math.h>
#include <stdint.h>

#define NN 50000
#define EE 800000
#define DD 128
#define NB 5
#define GG 512
#define NC 10
#define FD (NB*DD)            // 640
#define ONE_PLUS_EPS 129.0f
#define BN_EPS 1e-5f

#define MTILE 128
#define NTILES ((NN + MTILE - 1) / MTILE)   // 391

// ---------------- scratch (static device globals; no allocation) ----------------
__device__ __align__(16) float g_xcur[NN*DD];
__device__ __align__(16) float g_h0[NN*DD];
__device__ __align__(16) float g_hp1[NN*DD];
__device__ __align__(16) float g_hp2[NN*DD];
__device__ __align__(16) float g_feats[GG*FD];
__device__ __align__(16) float g_stats[2*DD];
__device__ __align__(16) float g_scale[DD];
__device__ __align__(16) float g_shift[DD];
__device__ float g_cscale[FD];
__device__ float g_cshift[FD];
__device__ __align__(16) float g_fmlp[GG*DD];
__device__ int g_src[EE];
__device__ int g_dst[EE];
__device__ int g_batch[NN];
__device__ int g_rowptr[NN+1];
__device__ int g_cnt[NN];
__device__ int g_esrc[EE];
__device__ int g_is64;
// pre-converted transposed weights: [10 mats][n=128][k=128] bf16 bits (hi/lo split)
__device__ __align__(16) unsigned short g_wthi[10*DD*DD];
__device__ __align__(16) unsigned short g_wtlo[10*DD*DD];

__device__ __forceinline__ uint32_t pack_bf16x2(float lo, float hi) {
    uint32_t r; asm("cvt.rn.bf16x2.f32 %0, %1, %2;" : "=r"(r) : "f"(hi), "f"(lo)); return r;
}

// mma.sync m16n8k16 row.col bf16 -> fp32 accumulate (baseline sm_80+ PTX)
__device__ __forceinline__ void mma16816(float* c, const uint32_t* a, uint32_t b0, uint32_t b1) {
    asm volatile(
        "mma.sync.aligned.m16n8k16.row.col.f32.bf16.bf16.f32 "
        "{%0,%1,%2,%3}, {%4,%5,%6,%7}, {%8,%9}, {%0,%1,%2,%3};"
        : "+f"(c[0]), "+f"(c[1]), "+f"(c[2]), "+f"(c[3])
        : "r"(a[0]), "r"(a[1]), "r"(a[2]), "r"(a[3]), "r"(b0), "r"(b1));
}

// ---------------- dtype probe ----------------
__global__ void detect_kernel(const void* ei) {
    const int* p = (const int*)ei;
    int t = threadIdx.x;
    __shared__ int nz;
    if (t == 0) nz = 0;
    __syncthreads();
    if (p[2*t + 1] != 0) atomicOr(&nz, 1);
    __syncthreads();
    if (t == 0) g_is64 = nz ? 0 : 1;
}

__global__ void convert_kernel(const void* ei, const void* bt) {
    int idx = blockIdx.x * blockDim.x + threadIdx.x;
    int is64 = g_is64;
    const int* p = (const int*)ei;
    const int* b = (const int*)bt;
    if (idx < EE) {
        if (is64) { g_src[idx] = p[2*idx]; g_dst[idx] = p[2*(EE+idx)]; }
        else      { g_src[idx] = p[idx];   g_dst[idx] = p[EE+idx]; }
    }
    if (idx < NN) g_batch[idx] = is64 ? b[2*idx] : b[idx];
}

// ---------------- init ----------------
__global__ void init_kernel(const float* __restrict__ x) {
    int idx = blockIdx.x * blockDim.x + threadIdx.x;
    if (idx < NN*DD) g_xcur[idx] = x[idx];
    if (idx < GG*FD) g_feats[idx] = 0.f;
    if (idx < NN)    g_cnt[idx] = 0;
    if (idx < 2*DD)  g_stats[idx] = 0.f;
}

// ---------------- weight split (once): Wt[n][k] = split(W[k][n]) ----------------
__global__ void wconv_kernel(const float* __restrict__ W1, const float* __restrict__ W2) {
    int idx = blockIdx.x * blockDim.x + threadIdx.x;
    if (idx >= 10*DD*DD) return;
    int mat = idx >> 14, rem = idx & 16383;
    int n = rem >> 7, k = rem & 127;
    const float* W = (mat < NB) ? (W1 + mat*DD*DD) : (W2 + (mat-NB)*DD*DD);
    float v = W[k*DD + n];
    __nv_bfloat16 hv = __float2bfloat16(v);
    float hf = __bfloat162float(hv);
    __nv_bfloat16 lv = __float2bfloat16(v - hf);
    g_wthi[idx] = *(unsigned short*)&hv;
    g_wtlo[idx] = *(unsigned short*)&lv;
}

// ---------------- CSR build ----------------
__global__ void hist_kernel() {
    int e = blockIdx.x * blockDim.x + threadIdx.x;
    if (e < EE) atomicAdd(&g_cnt[g_dst[e]], 1);
}

__global__ void scan_kernel() {
    __shared__ int s[1024];
    __shared__ int carry;
    int t = threadIdx.x;
    if (t == 0) carry = 0;
    __syncthreads();
    for (int base = 0; base <= NN; base += 1024) {
        int i = base + t;
        int v = (i < NN) ? g_cnt[i] : 0;
        s[t] = v;
        __syncthreads();
        for (int off = 1; off < 1024; off <<= 1) {
            int tmp = (t >= off) ? s[t - off] : 0;
            __syncthreads();
            s[t] += tmp;
            __syncthreads();
        }
        if (i <= NN) g_rowptr[i] = carry + s[t] - v;
        if (i < NN)  g_cnt[i] = 0;
        __syncthreads();
        if (t == 0) carry += s[1023];
        __syncthreads();
    }
}

__global__ void scatter_kernel() {
    int e = blockIdx.x * blockDim.x + threadIdx.x;
    if (e < EE) {
        int d = g_dst[e];
        int pos = g_rowptr[d] + atomicAdd(&g_cnt[d], 1);
        g_esrc[pos] = g_src[e];
    }
}

// ---------------- GIN aggregation: warp per node, float4 ----------------
__global__ void agg_kernel() {
    int w = (blockIdx.x * blockDim.x + threadIdx.x) >> 5;
    int lane = threadIdx.x & 31;
    if (w >= NN) return;
    int beg = g_rowptr[w], end = g_rowptr[w+1];
    const float4* x4 = (const float4*)g_xcur;
    float4 me = x4[w*32 + lane];
    float4 acc;
    acc.x = ONE_PLUS_EPS * me.x; acc.y = ONE_PLUS_EPS * me.y;
    acc.z = ONE_PLUS_EPS * me.z; acc.w = ONE_PLUS_EPS * me.w;
    for (int base = beg; base < end; base += 32) {
        int n = min(32, end - base);
        int s = (lane < n) ? g_esrc[base + lane] : 0;
        for (int j = 0; j < n; j++) {
            int sj = __shfl_sync(0xffffffffu, s, j);
            float4 v = x4[sj*32 + lane];
            acc.x += v.x; acc.y += v.y; acc.z += v.z; acc.w += v.w;
        }
    }
    ((float4*)g_h0)[w*32 + lane] = acc;
}

// ---------------- mma.sync GEMM: out = relu([bn](A) @ W + b) ----------------
// A [128 x 128] fp32 -> hi/lo bf16 in SMEM (row-major, padded rows of 136 halves)
// W^T [n=128][k=128] hi/lo bf16 in SMEM (same padding)
// 8 warps: warp (w&3) -> 32-row strip, (w>>2) -> 64-col strip
#define PADK 136
#define SM_BIAS 0
#define SM_AHI  512
#define SM_ALO  (SM_AHI + DD*PADK*2)      // +34816
#define SM_WHI  (SM_ALO + DD*PADK*2)
#define SM_WLO  (SM_WHI + DD*PADK*2)
#define SM_TOTAL (SM_WLO + DD*PADK*2)     // 139776 bytes

#define LDH(base, r, c) (*(const uint32_t*)(smem + (base) + ((r)*PADK + (c))*2))

template<int PHASE>
__global__ void __launch_bounds__(256, 1) gemm_mma_kernel(const float* __restrict__ bias, int mat)
{
    extern __shared__ char smem[];
    const float* A = (PHASE == 0) ? g_h0 : g_hp1;
    float* out     = (PHASE == 0) ? g_hp1 : g_hp2;
    int t = threadIdx.x, wid = t >> 5, l = t & 31;
    int row0 = blockIdx.x * MTILE;

    if (t < DD) *(float*)(smem + SM_BIAS + t*4) = bias[t];

    // W tiles (pre-split bf16 [n][k]): 2048 uint4 per matrix
    {
        const uint4* whi = (const uint4*)(g_wthi + mat*DD*DD);
        const uint4* wlo = (const uint4*)(g_wtlo + mat*DD*DD);
        #pragma unroll
        for (int lp = 0; lp < 8; lp++) {
            int i = t + lp*256;
            int n = i >> 4, k8 = i & 15;
            uint32_t off = (uint32_t)(n*PADK + k8*8) * 2;
            *(uint4*)(smem + SM_WHI + off) = whi[i];
            *(uint4*)(smem + SM_WLO + off) = wlo[i];
        }
    }

    // A tile: fp32 load, optional bn, hi/lo bf16 split
    #pragma unroll
    for (int lp = 0; lp < 16; lp++) {
        int i = t + lp*256;
        int r = i >> 5, f4 = i & 31;
        int gr = row0 + r;
        float4 a = make_float4(0.f, 0.f, 0.f, 0.f);
        if (gr < NN) a = __ldg((const float4*)A + gr*32 + f4);
        if (PHASE == 1) {
            float4 sc = *(const float4*)(g_scale + f4*4);
            float4 sh = *(const float4*)(g_shift + f4*4);
            a.x = fmaf(a.x, sc.x, sh.x); a.y = fmaf(a.y, sc.y, sh.y);
            a.z = fmaf(a.z, sc.z, sh.z); a.w = fmaf(a.w, sc.w, sh.w);
        }
        uint32_t h01 = pack_bf16x2(a.x, a.y);
        uint32_t h23 = pack_bf16x2(a.z, a.w);
        float rx = a.x - __uint_as_float(h01 << 16);
        float ry = a.y - __uint_as_float(h01 & 0xFFFF0000u);
        float rz = a.z - __uint_as_float(h23 << 16);
        float rw = a.w - __uint_as_float(h23 & 0xFFFF0000u);
        uint32_t l01 = pack_bf16x2(rx, ry);
        uint32_t l23 = pack_bf16x2(rz, rw);
        uint32_t off = (uint32_t)(r*PADK + f4*4) * 2;
        *(uint2*)(smem + SM_AHI + off) = make_uint2(h01, h23);
        *(uint2*)(smem + SM_ALO + off) = make_uint2(l01, l23);
    }
    __syncthreads();

    int mrow0 = (wid & 3) * 32;
    int ncol0 = (wid >> 2) * 64;
    float acc[2][8][4];
    #pragma unroll
    for (int mt = 0; mt < 2; mt++)
        #pragma unroll
        for (int nt = 0; nt < 8; nt++)
            #pragma unroll
            for (int j = 0; j < 4; j++) acc[mt][nt][j] = 0.f;

    #pragma unroll 2
    for (int ks = 0; ks < 8; ks++) {
        int k0 = ks * 16;
        uint32_t ahi[2][4], alo[2][4];
        #pragma unroll
        for (int mt = 0; mt < 2; mt++) {
            int r0 = mrow0 + mt*16 + (l >> 2);
            int c0 = k0 + (l & 3)*2;
            ahi[mt][0] = LDH(SM_AHI, r0,     c0);
            ahi[mt][1] = LDH(SM_AHI, r0 + 8, c0);
            ahi[mt][2] = LDH(SM_AHI, r0,     c0 + 8);
            ahi[mt][3] = LDH(SM_AHI, r0 + 8, c0 + 8);
            alo[mt][0] = LDH(SM_ALO, r0,     c0);
            alo[mt][1] = LDH(SM_ALO, r0 + 8, c0);
            alo[mt][2] = LDH(SM_ALO, r0,     c0 + 8);
            alo[mt][3] = LDH(SM_ALO, r0 + 8, c0 + 8);
        }
        #pragma unroll
        for (int nt = 0; nt < 8; nt++) {
            int n0 = ncol0 + nt*8 + (l >> 2);
            int ck = k0 + (l & 3)*2;
            uint32_t bh0 = LDH(SM_WHI, n0, ck);
            uint32_t bh1 = LDH(SM_WHI, n0, ck + 8);
            uint32_t bl0 = LDH(SM_WLO, n0, ck);
            uint32_t bl1 = LDH(SM_WLO, n0, ck + 8);
            #pragma unroll
            for (int mt = 0; mt < 2; mt++) {
                mma16816(acc[mt][nt], ahi[mt], bh0, bh1);
                mma16816(acc[mt][nt], ahi[mt], bl0, bl1);
                mma16816(acc[mt][nt], alo[mt], bh0, bh1);
            }
        }
    }

    // epilogue: bias + relu + store
    const float* sbias = (const float*)(smem + SM_BIAS);
    #pragma unroll
    for (int mt = 0; mt < 2; mt++) {
        int r = mrow0 + mt*16 + (l >> 2);
        int gr0 = row0 + r;
        int gr1 = gr0 + 8;
        #pragma unroll
        for (int nt = 0; nt < 8; nt++) {
            int c = ncol0 + nt*8 + (l & 3)*2;
            float bx = sbias[c], by = sbias[c+1];
            if (gr0 < NN) {
                float2 v0;
                v0.x = fmaxf(acc[mt][nt][0] + bx, 0.f);
                v0.y = fmaxf(acc[mt][nt][1] + by, 0.f);
                *(float2*)(out + gr0*DD + c) = v0;
            }
            if (gr1 < NN) {
                float2 v1;
                v1.x = fmaxf(acc[mt][nt][2] + bx, 0.f);
                v1.y = fmaxf(acc[mt][nt][3] + by, 0.f);
                *(float2*)(out + gr1*DD + c) = v1;
            }
        }
    }
}

// ---------------- column stats over [NN x 128] (L2-resident pass) ----------------
template<int WHICH>
__global__ void stats_kernel() {
    const float* h = (WHICH == 1) ? g_hp1 : g_hp2;
    __shared__ float4 ss[256], sq[256];
    int t = threadIdx.x;
    int f4 = t & 31, rg = t >> 5;
    float4 s = make_float4(0,0,0,0), q = make_float4(0,0,0,0);
    for (int row = blockIdx.x*8 + rg; row < NN; row += gridDim.x*8) {
        float4 v = ((const float4*)h)[row*32 + f4];
        s.x += v.x; s.y += v.y; s.z += v.z; s.w += v.w;
        q.x += v.x*v.x; q.y += v.y*v.y; q.z += v.z*v.z; q.w += v.w*v.w;
    }
    ss[t] = s; sq[t] = q;
    __syncthreads();
    for (int off = 128; off >= 32; off >>= 1) {
        if (t < off) {
            float4 a = ss[t+off], b = sq[t+off];
            ss[t].x += a.x; ss[t].y += a.y; ss[t].z += a.z; ss[t].w += a.w;
            sq[t].x += b.x; sq[t].y += b.y; sq[t].z += b.z; sq[t].w += b.w;
        }
        __syncthreads();
    }
    if (t < 32) {
        float4 S = ss[t], Q = sq[t];
        atomicAdd(&g_stats[t*4+0], S.x); atomicAdd(&g_stats[t*4+1], S.y);
        atomicAdd(&g_stats[t*4+2], S.z); atomicAdd(&g_stats[t*4+3], S.w);
        atomicAdd(&g_stats[DD+t*4+0], Q.x); atomicAdd(&g_stats[DD+t*4+1], Q.y);
        atomicAdd(&g_stats[DD+t*4+2], Q.z); atomicAdd(&g_stats[DD+t*4+3], Q.w);
    }
}

__global__ void finalize_kernel(const float* __restrict__ gamma,
                                const float* __restrict__ beta)
{
    int t = threadIdx.x;  // 128
    float s  = g_stats[t];
    float sq = g_stats[DD + t];
    float mu  = s / (float)NN;
    float var = sq / (float)NN - mu*mu;
    float r   = rsqrtf(var + BN_EPS);
    float sc  = gamma[t] * r;
    g_scale[t] = sc;
    g_shift[t] = beta[t] - mu*sc;
    g_stats[t] = 0.f;
    g_stats[DD + t] = 0.f;
}

// ---------------- bn apply + pool ----------------
__global__ void bnpool_kernel(int blk) {
    int idx = blockIdx.x * blockDim.x + threadIdx.x;
    if (idx >= NN*DD) return;
    int n = idx >> 7, d = idx & 127;
    float v = g_hp2[idx] * g_scale[d] + g_shift[d];
    g_xcur[idx] = v;
    atomicAdd(&g_feats[g_batch[n]*FD + blk*DD + d], v);
}

// ---------------- classifier head ----------------
__global__ void cstats_kernel(const float* __restrict__ bn_g,
                              const float* __restrict__ bn_b)
{
    int c = blockIdx.x;
    int t = threadIdx.x;
    float s = 0.f, sq = 0.f;
    for (int r = t; r < GG; r += 256) {
        float v = g_feats[r*FD + c];
        s += v; sq += v*v;
    }
    __shared__ float rs[256], rq[256];
    rs[t] = s; rq[t] = sq;
    __syncthreads();
    for (int off = 128; off > 0; off >>= 1) {
        if (t < off) { rs[t] += rs[t+off]; rq[t] += rq[t+off]; }
        __syncthreads();
    }
    if (t == 0) {
        float mu  = rs[0] / (float)GG;
        float var = rq[0] / (float)GG - mu*mu;
        float r   = rsqrtf(var + BN_EPS);
        float sc  = bn_g[c] * r;
        g_cscale[c] = sc;
        g_cshift[c] = bn_b[c] - mu*sc;
    }
}

__global__ void mlp1_kernel(const float* __restrict__ Wc1,
                            const float* __restrict__ bc1)
{
    int row = blockIdx.x;
    int t = threadIdx.x;
    __shared__ float sf[DD];
    float acc = 0.f;
    for (int kb = 0; kb < NB; kb++) {
        int k = kb*DD + t;
        sf[t] = g_feats[row*FD + k] * g_cscale[k] + g_cshift[k];
        __syncthreads();
        #pragma unroll 8
        for (int kk = 0; kk < DD; kk++)
            acc += sf[kk] * Wc1[(kb*DD + kk)*DD + t];
        __syncthreads();
    }
    g_fmlp[row*DD + t] = fmaxf(acc + bc1[t], 0.f);
}

__global__ void mlp2_kernel(const float* __restrict__ Wc2,
                            const float* __restrict__ bc2,
                            float* __restrict__ out)
{
    int warp = (blockIdx.x * blockDim.x + threadIdx.x) >> 5;
    int lane = threadIdx.x & 31;
    if (warp >= GG) return;
    float p[NC];
    #pragma unroll
    for (int c = 0; c < NC; c++) p[c] = 0.f;
    for (int k = lane; k < DD; k += 32) {
        float a = g_fmlp[warp*DD + k];
        #pragma unroll
        for (int c = 0; c < NC; c++) p[c] += a * Wc2[k*NC + c];
    }
    #pragma unroll
    for (int c = 0; c < NC; c++)
        #pragma unroll
        for (int off = 16; off > 0; off >>= 1)
            p[c] += __shfl_down_sync(0xffffffff, p[c], off);
    if (lane == 0) {
        float logits[NC];
        float mx = -1e30f;
        #pragma unroll
        for (int c = 0; c < NC; c++) { logits[c] = p[c] + bc2[c]; mx = fmaxf(mx, logits[c]); }
        float s = 0.f;
        #pragma unroll
        for (int c = 0; c < NC; c++) s += expf(logits[c] - mx);
        float lse = logf(s) + mx;
        #pragma unroll
        for (int c = 0; c < NC; c++) out[warp*NC + c] = logits[c] - lse;
    }
}

// ---------------- launch ----------------
extern "C" void kernel_launch(void* const* d_in, const int* in_sizes, int n_in,
                              void* d_out, int out_size)
{
    const float* x    = (const float*)d_in[0];
    const void*  ei   = d_in[1];
    const void*  bt   = d_in[2];
    const float* W1   = (const float*)d_in[3];
    const float* b1   = (const float*)d_in[4];
    const float* g1   = (const float*)d_in[5];
    const float* be1  = (const float*)d_in[6];
    const float* W2   = (const float*)d_in[7];
    const float* b2   = (const float*)d_in[8];
    const float* g2   = (const float*)d_in[9];
    const float* be2  = (const float*)d_in[10];
    const float* bng  = (const float*)d_in[11];
    const float* bnb  = (const float*)d_in[12];
    const float* Wc1  = (const float*)d_in[13];
    const float* bc1  = (const float*)d_in[14];
    const float* Wc2  = (const float*)d_in[15];
    const float* bc2  = (const float*)d_in[16];
    float* out = (float*)d_out;

    static int attr_done = 0;
    if (!attr_done) {
        cudaFuncSetAttribute(gemm_mma_kernel<0>, cudaFuncAttributeMaxDynamicSharedMemorySize, SM_TOTAL);
        cudaFuncSetAttribute(gemm_mma_kernel<1>, cudaFuncAttributeMaxDynamicSharedMemorySize, SM_TOTAL);
        attr_done = 1;
    }

    detect_kernel<<<1, 128>>>(ei);
    convert_kernel<<<(EE + 255)/256, 256>>>(ei, bt);
    init_kernel<<<(NN*DD + 255)/256, 256>>>(x);
    wconv_kernel<<<(10*DD*DD + 255)/256, 256>>>(W1, W2);
    hist_kernel<<<(EE + 255)/256, 256>>>();
    scan_kernel<<<1, 1024>>>();
    scatter_kernel<<<(EE + 255)/256, 256>>>();

    for (int i = 0; i < NB; i++) {
        agg_kernel<<<(NN*32 + 255)/256, 256>>>();
        gemm_mma_kernel<0><<<NTILES, 256, SM_TOTAL>>>(b1 + i*DD, i);
        stats_kernel<1><<<592, 256>>>();
        finalize_kernel<<<1, 128>>>(g1 + i*DD, be1 + i*DD);
        gemm_mma_kernel<1><<<NTILES, 256, SM_TOTAL>>>(b2 + i*DD, NB + i);
        stats_kernel<2><<<592, 256>>>();
        finalize_kernel<<<1, 128>>>(g2 + i*DD, be2 + i*DD);
        bnpool_kernel<<<(NN*DD + 255)/256, 256>>>(i);
    }

    cstats_kernel<<<FD, 256>>>(bng, bnb);
    mlp1_kernel<<<GG, 128>>>(Wc1, bc1);
    mlp2_kernel<<<(GG*32 + 255)/256, 256>>>(Wc2, bc2, out);
}